// round 2
// baseline (speedup 1.0000x reference)
#include <cuda_runtime.h>

static constexpr int N_TOK = 4096;
static constexpr int DIM   = 1024;
static constexpr int HID   = 4096;
static constexpr int NEXP  = 8;

// Scratch (static __device__ — allocation-free, graph-safe)
__device__ int   g_cnt[NEXP];
__device__ int   g_tok[NEXP * N_TOK];
__device__ float g_wt [NEXP * N_TOK];
__device__ float g_h  [(long long)NEXP * N_TOK * HID];   // per-(expert,slot) hidden acts

// ---------------------------------------------------------------------------
// Zero output + expert counters
// ---------------------------------------------------------------------------
__global__ void zero_kernel(float* __restrict__ out, long long n) {
    long long i = (long long)blockIdx.x * blockDim.x + threadIdx.x;
    if (i < n) out[i] = 0.f;
    if (blockIdx.x == 0 && threadIdx.x < NEXP) g_cnt[threadIdx.x] = 0;
}

// ---------------------------------------------------------------------------
// Gating: 1 warp per token. logits = x@Wg + bg, softmax over 8, top-2,
// scatter (token, weight) into per-expert lists.
// ---------------------------------------------------------------------------
__global__ void gate_kernel(const float* __restrict__ x,
                            const float* __restrict__ Wg,
                            const float* __restrict__ bg) {
    int warp = (blockIdx.x * blockDim.x + threadIdx.x) >> 5;
    int lane = threadIdx.x & 31;
    if (warp >= N_TOK) return;
    const float* xr = x + (long long)warp * DIM;

    float acc[NEXP];
#pragma unroll
    for (int e = 0; e < NEXP; e++) acc[e] = 0.f;
    for (int d = lane; d < DIM; d += 32) {
        float xv = xr[d];
        const float* wr = Wg + d * NEXP;
#pragma unroll
        for (int e = 0; e < NEXP; e++) acc[e] += xv * wr[e];
    }
#pragma unroll
    for (int off = 16; off > 0; off >>= 1)
#pragma unroll
        for (int e = 0; e < NEXP; e++)
            acc[e] += __shfl_down_sync(0xffffffffu, acc[e], off);

    if (lane == 0) {
        float m = -1e30f;
#pragma unroll
        for (int e = 0; e < NEXP; e++) { acc[e] += bg[e]; m = fmaxf(m, acc[e]); }
        float p[NEXP];
        float s = 0.f;
#pragma unroll
        for (int e = 0; e < NEXP; e++) { p[e] = expf(acc[e] - m); s += p[e]; }
        float inv = 1.f / s;
        // top-1 (first max => lowest index on ties, matching jax top_k order)
        int e0 = 0; float v0 = p[0];
#pragma unroll
        for (int e = 1; e < NEXP; e++) if (p[e] > v0) { v0 = p[e]; e0 = e; }
        // top-2
        int e1 = -1; float v1 = -1.f;
#pragma unroll
        for (int e = 0; e < NEXP; e++)
            if (e != e0 && p[e] > v1) { v1 = p[e]; e1 = e; }

        int s0 = atomicAdd(&g_cnt[e0], 1);
        g_tok[e0 * N_TOK + s0] = warp;
        g_wt [e0 * N_TOK + s0] = v0 * inv;
        int s1 = atomicAdd(&g_cnt[e1], 1);
        g_tok[e1 * N_TOK + s1] = warp;
        g_wt [e1 * N_TOK + s1] = v1 * inv;
    }
}

// ---------------------------------------------------------------------------
// Grouped SGEMM, 128x128 tile, BK=8, 256 threads, 8x8 microtile.
// MODE 1: h[e,slot,:] = relu(x[tok]@W1[e] + b1[e])      (A = gathered x rows)
// MODE 2: out[tok,:] += w * (h[e,slot,:]@W2[e] + b2[e]) (A = g_h rows, atomic)
// ---------------------------------------------------------------------------
template <int MODE>
__global__ __launch_bounds__(256, 2)
void moe_gemm(const float* __restrict__ Abase,   // x (MODE 1) / unused (MODE 2)
              const float* __restrict__ Wbase,   // W1 / W2
              const float* __restrict__ bias,    // b1 [E,HID] / b2 [E,DIM]
              float* __restrict__ Cbase,         // unused (MODE 1) / out (MODE 2)
              int K, int NCOL)
{
    const int e   = blockIdx.z;
    const int cnt = g_cnt[e];
    const int rt  = blockIdx.y;
    if (rt * 128 >= cnt) return;
    const int nt = blockIdx.x;

    __shared__ float As[8 * 128];
    __shared__ float Bs[8 * 128];

    const float* B = Wbase + (long long)e * K * NCOL + nt * 128;

    const int t    = threadIdx.x;
    const int arow = t >> 1;          // 0..127
    const int ak   = (t & 1) * 4;     // 0 or 4
    const int brow = t >> 5;          // 0..7
    const int bcol = (t & 31) * 4;    // 0..124

    const int  grow   = rt * 128 + arow;
    const bool avalid = grow < cnt;
    const float* Arow;
    if (MODE == 1) {
        int tokn = avalid ? g_tok[e * N_TOK + grow] : 0;
        Arow = Abase + (long long)tokn * K;
    } else {
        Arow = g_h + ((long long)e * N_TOK + (avalid ? grow : 0)) * (long long)K;
    }

    const int tx = t & 15, ty = t >> 4;
    float acc[8][8];
#pragma unroll
    for (int i = 0; i < 8; i++)
#pragma unroll
        for (int j = 0; j < 8; j++) acc[i][j] = 0.f;

    for (int k0 = 0; k0 < K; k0 += 8) {
        float4 av = avalid ? *(const float4*)(Arow + k0 + ak)
                           : make_float4(0.f, 0.f, 0.f, 0.f);
        float4 bv = *(const float4*)(B + (long long)(k0 + brow) * NCOL + bcol);
        As[(ak + 0) * 128 + arow] = av.x;
        As[(ak + 1) * 128 + arow] = av.y;
        As[(ak + 2) * 128 + arow] = av.z;
        As[(ak + 3) * 128 + arow] = av.w;
        *(float4*)&Bs[brow * 128 + bcol] = bv;
        __syncthreads();
#pragma unroll
        for (int k = 0; k < 8; k++) {
            float a[8], b[8];
#pragma unroll
            for (int i = 0; i < 8; i++) a[i] = As[k * 128 + ty * 8 + i];
#pragma unroll
            for (int j = 0; j < 8; j++) b[j] = Bs[k * 128 + tx * 8 + j];
#pragma unroll
            for (int i = 0; i < 8; i++)
#pragma unroll
                for (int j = 0; j < 8; j++) acc[i][j] += a[i] * b[j];
        }
        __syncthreads();
    }

    const int colbase = nt * 128 + tx * 8;
    if (MODE == 1) {
#pragma unroll
        for (int i = 0; i < 8; i++) {
            int row = rt * 128 + ty * 8 + i;
            if (row < cnt) {
                long long obase = ((long long)e * N_TOK + row) * (long long)NCOL + colbase;
#pragma unroll
                for (int j = 0; j < 8; j++) {
                    float v = acc[i][j] + bias[e * NCOL + colbase + j];
                    g_h[obase + j] = v > 0.f ? v : 0.f;
                }
            }
        }
    } else {
#pragma unroll
        for (int i = 0; i < 8; i++) {
            int row = rt * 128 + ty * 8 + i;
            if (row < cnt) {
                int   tokn = g_tok[e * N_TOK + row];
                float w    = g_wt [e * N_TOK + row];
                long long obase = (long long)tokn * NCOL + colbase;
#pragma unroll
                for (int j = 0; j < 8; j++)
                    atomicAdd(&Cbase[obase + j],
                              w * (acc[i][j] + bias[e * NCOL + colbase + j]));
            }
        }
    }
}

// ---------------------------------------------------------------------------
extern "C" void kernel_launch(void* const* d_in, const int* /*in_sizes*/, int /*n_in*/,
                              void* d_out, int /*out_size*/) {
    const float* x  = (const float*)d_in[0];
    const float* Wg = (const float*)d_in[1];
    const float* bg = (const float*)d_in[2];
    const float* W1 = (const float*)d_in[3];
    const float* b1 = (const float*)d_in[4];
    const float* W2 = (const float*)d_in[5];
    const float* b2 = (const float*)d_in[6];
    float* out = (float*)d_out;

    const long long nout = (long long)N_TOK * DIM;
    zero_kernel<<<(unsigned)((nout + 255) / 256), 256>>>(out, nout);
    gate_kernel<<<N_TOK / 8, 256>>>(x, Wg, bg);

    // GEMM1: h = relu(x@W1 + b1), per expert over its token list
    moe_gemm<1><<<dim3(HID / 128, N_TOK / 128, NEXP), 256>>>(x, W1, b1, nullptr, DIM, HID);
    // GEMM2: out += w * (h@W2 + b2)
    moe_gemm<2><<<dim3(DIM / 128, N_TOK / 128, NEXP), 256>>>(nullptr, W2, b2, out, HID, DIM);
}

// round 4
// speedup vs baseline: 2.6290x; 2.6290x over previous
#include <cuda_runtime.h>
#include <cuda_bf16.h>
#include <cstdint>
#include <cstddef>

static constexpr int N_TOK = 4096;
static constexpr int DIM   = 1024;
static constexpr int HID   = 4096;
static constexpr int NEXP  = 8;

// ---------------------------------------------------------------------------
// Static device scratch (allocation-free, graph-safe)
// ---------------------------------------------------------------------------
__device__ int   g_cnt[NEXP];
__device__ int   g_tok[NEXP * N_TOK];
__device__ int   g_pos[NEXP * N_TOK];
__device__ float g_wt [NEXP * N_TOK];

__device__ __align__(16) __nv_bfloat16 g_x_hi[(size_t)N_TOK * DIM];
__device__ __align__(16) __nv_bfloat16 g_x_lo[(size_t)N_TOK * DIM];
__device__ __align__(16) __nv_bfloat16 g_w1_hi[(size_t)NEXP * HID * DIM]; // [E][H][D]
__device__ __align__(16) __nv_bfloat16 g_w1_lo[(size_t)NEXP * HID * DIM];
__device__ __align__(16) __nv_bfloat16 g_w2_hi[(size_t)NEXP * DIM * HID]; // [E][D][H]
__device__ __align__(16) __nv_bfloat16 g_w2_lo[(size_t)NEXP * DIM * HID];
__device__ __align__(16) __nv_bfloat16 g_h_hi[(size_t)NEXP * N_TOK * HID];
__device__ __align__(16) __nv_bfloat16 g_h_lo[(size_t)NEXP * N_TOK * HID];
__device__ __align__(16) float         g_y   [(size_t)2 * N_TOK * DIM];

// ---------------------------------------------------------------------------
// PTX helpers (all plain sm_80-level: compile under target sm_103 w/o 'a')
// ---------------------------------------------------------------------------
__device__ __forceinline__ uint32_t smem_u32(const void* p) {
    uint32_t a;
    asm("{ .reg .u64 t; cvta.to.shared.u64 t, %1; cvt.u32.u64 %0, t; }" : "=r"(a) : "l"(p));
    return a;
}
#define CP_ASYNC16(dst, src) \
    asm volatile("cp.async.cg.shared.global [%0], [%1], 16;" :: "r"(dst), "l"(src))
#define CP_COMMIT() asm volatile("cp.async.commit_group;" ::: "memory")
#define CP_WAIT1()  asm volatile("cp.async.wait_group 1;" ::: "memory")

#define LDMX4(r, a)                                                              \
    asm volatile("ldmatrix.sync.aligned.m8n8.x4.shared.b16 {%0,%1,%2,%3}, [%4];" \
        : "=r"((r)[0]), "=r"((r)[1]), "=r"((r)[2]), "=r"((r)[3]) : "r"(a))

#define MMA16816(d, a, b0, b1)                                                   \
    asm volatile("mma.sync.aligned.m16n8k16.row.col.f32.bf16.bf16.f32 "          \
        "{%0,%1,%2,%3},{%4,%5,%6,%7},{%8,%9},{%0,%1,%2,%3};"                     \
        : "+f"((d)[0]), "+f"((d)[1]), "+f"((d)[2]), "+f"((d)[3])                 \
        : "r"((a)[0]), "r"((a)[1]), "r"((a)[2]), "r"((a)[3]), "r"(b0), "r"(b1))

__device__ __forceinline__ uint32_t sw128(uint32_t off) {
    return off ^ ((off >> 3) & 0x70);
}

// ---------------------------------------------------------------------------
// Init counters
// ---------------------------------------------------------------------------
__global__ void initcnt_kernel() {
    if (threadIdx.x < NEXP) g_cnt[threadIdx.x] = 0;
}

// ---------------------------------------------------------------------------
// Gating: 1 warp/token, softmax(8), top-2, scatter + position tag
// ---------------------------------------------------------------------------
__global__ void gate_kernel(const float* __restrict__ x,
                            const float* __restrict__ Wg,
                            const float* __restrict__ bg) {
    int warp = (blockIdx.x * blockDim.x + threadIdx.x) >> 5;
    int lane = threadIdx.x & 31;
    if (warp >= N_TOK) return;
    const float* xr = x + (long long)warp * DIM;

    float acc[NEXP];
#pragma unroll
    for (int e = 0; e < NEXP; e++) acc[e] = 0.f;
    for (int d = lane; d < DIM; d += 32) {
        float xv = xr[d];
        const float* wr = Wg + d * NEXP;
#pragma unroll
        for (int e = 0; e < NEXP; e++) acc[e] += xv * wr[e];
    }
#pragma unroll
    for (int off = 16; off > 0; off >>= 1)
#pragma unroll
        for (int e = 0; e < NEXP; e++)
            acc[e] += __shfl_down_sync(0xffffffffu, acc[e], off);

    if (lane == 0) {
        float m = -1e30f;
#pragma unroll
        for (int e = 0; e < NEXP; e++) { acc[e] += bg[e]; m = fmaxf(m, acc[e]); }
        float p[NEXP]; float s = 0.f;
#pragma unroll
        for (int e = 0; e < NEXP; e++) { p[e] = expf(acc[e] - m); s += p[e]; }
        float inv = 1.f / s;
        int e0 = 0; float v0 = p[0];
#pragma unroll
        for (int e = 1; e < NEXP; e++) if (p[e] > v0) { v0 = p[e]; e0 = e; }
        int e1 = -1; float v1 = -1.f;
#pragma unroll
        for (int e = 0; e < NEXP; e++) if (e != e0 && p[e] > v1) { v1 = p[e]; e1 = e; }

        int s0 = atomicAdd(&g_cnt[e0], 1);
        g_tok[e0 * N_TOK + s0] = warp;
        g_wt [e0 * N_TOK + s0] = v0 * inv;
        g_pos[e0 * N_TOK + s0] = 0;
        int s1 = atomicAdd(&g_cnt[e1], 1);
        g_tok[e1 * N_TOK + s1] = warp;
        g_wt [e1 * N_TOK + s1] = v1 * inv;
        g_pos[e1 * N_TOK + s1] = 1;
    }
}

// ---------------------------------------------------------------------------
// fp32 -> bf16 hi/lo split for x
// ---------------------------------------------------------------------------
__global__ void split_x_kernel(const float* __restrict__ x) {
    size_t i = (size_t)blockIdx.x * blockDim.x + threadIdx.x;
    float v = x[i];
    __nv_bfloat16 h = __float2bfloat16(v);
    g_x_hi[i] = h;
    g_x_lo[i] = __float2bfloat16(v - __bfloat162float(h));
}

// ---------------------------------------------------------------------------
// Weight transpose+split:  in [E][R][C] fp32 -> out [E][C][R] bf16 hi/lo
// ---------------------------------------------------------------------------
__global__ void wsplit_kernel(const float* __restrict__ in, int R, int C, int which) {
    __shared__ float t[32][33];
    __nv_bfloat16* hi = (which == 1) ? g_w1_hi : g_w2_hi;
    __nv_bfloat16* lo = (which == 1) ? g_w1_lo : g_w2_lo;
    int e = blockIdx.z;
    int r0 = blockIdx.y * 32, c0 = blockIdx.x * 32;
    const float* src = in + (size_t)e * R * C;
    for (int j = threadIdx.y; j < 32; j += 8)
        t[j][threadIdx.x] = src[(size_t)(r0 + j) * C + c0 + threadIdx.x];
    __syncthreads();
    size_t ob = (size_t)e * C * R;
    for (int j = threadIdx.y; j < 32; j += 8) {
        float v = t[threadIdx.x][j];
        size_t o = ob + (size_t)(c0 + j) * R + r0 + threadIdx.x;
        __nv_bfloat16 h = __float2bfloat16(v);
        hi[o] = h;
        lo[o] = __float2bfloat16(v - __bfloat162float(h));
    }
}

// ---------------------------------------------------------------------------
// Grouped HMMA GEMM.  CTA tile 128x128, K-chunk 64 (hi+lo), 3-stage cp.async
// pipeline, 8 warps (2x4), warp tile 64x32, mma.m16n8k16 bf16, fp32 acc.
// 3 products: Ahi*Bhi + Ahi*Blo + Alo*Bhi.
// MODE 1: h = relu(x@W1t + b1) -> g_h hi/lo        (A = gathered x rows)
// MODE 2: g_y[tok*2+pos] = w*(h@W2t + b2)          (A = g_h slots)
// ---------------------------------------------------------------------------
template <int MODE>
__global__ __launch_bounds__(256, 1)
void moe_hmma(const float* __restrict__ bias) {
    constexpr int K       = (MODE == 1) ? DIM : HID;
    constexpr int NCOL    = (MODE == 1) ? HID : DIM;
    constexpr int NCHUNK  = K / 64;
    constexpr uint32_t STAGE = 65536;   // Ahi 16K | Alo 16K | Bhi 16K | Blo 16K

    const int e   = blockIdx.z;
    const int cnt = g_cnt[e];
    const int rt  = blockIdx.y;
    if (rt * 128 >= cnt) return;
    const int nt = blockIdx.x;

    extern __shared__ char smem[];
    const uint32_t sdyn = smem_u32(smem);
    const int tid  = threadIdx.x;
    const int lane = tid & 31;
    const int wid  = tid >> 5;
    const int wm = (wid & 1) * 64;
    const int wn = (wid >> 1) * 32;

    const __nv_bfloat16* Ahi = (MODE == 1) ? g_x_hi  : g_h_hi;
    const __nv_bfloat16* Alo = (MODE == 1) ? g_x_lo  : g_h_lo;
    const __nv_bfloat16* Bhi = (MODE == 1) ? g_w1_hi : g_w2_hi;
    const __nv_bfloat16* Blo = (MODE == 1) ? g_w1_lo : g_w2_lo;
    const ptrdiff_t dAb = (const char*)Alo - (const char*)Ahi;
    const ptrdiff_t dBb = (const char*)Blo - (const char*)Bhi;

    // ------------------- cp.async load plan (per thread) --------------------
    const int u16 = (tid & 7) * 16;           // byte offset within 128B row
    const char* ap[4];
    const char* bp[4];
    uint32_t    dst[4];
#pragma unroll
    for (int i = 0; i < 4; i++) {
        int r    = (tid >> 3) + 32 * i;       // row within tile, 0..127
        int slot = rt * 128 + r; if (slot >= cnt) slot = cnt - 1;
        size_t arow = (MODE == 1) ? (size_t)g_tok[e * N_TOK + slot]
                                  : ((size_t)e * N_TOK + slot);
        ap[i] = (const char*)(Ahi + arow * (size_t)K) + u16;
        bp[i] = (const char*)(Bhi + ((size_t)e * NCOL + (size_t)nt * 128 + r) * (size_t)K) + u16;
        dst[i] = sw128((uint32_t)(r * 128) + (uint32_t)u16);
    }

    auto load_stage = [&](int s, int k0) {
        uint32_t st = sdyn + (uint32_t)s * STAGE;
        int kb = k0 * 2;
#pragma unroll
        for (int i = 0; i < 4; i++) {
            CP_ASYNC16(st + dst[i],         ap[i] + kb);
            CP_ASYNC16(st + 16384 + dst[i], ap[i] + dAb + kb);
            CP_ASYNC16(st + 32768 + dst[i], bp[i] + kb);
            CP_ASYNC16(st + 49152 + dst[i], bp[i] + dBb + kb);
        }
    };

    // ------------------- ldmatrix address precompute -------------------------
    uint32_t abase[4], amask[4];
#pragma unroll
    for (int mi = 0; mi < 4; mi++) {
        int r = wm + mi * 16 + (lane & 15);
        abase[mi] = (uint32_t)(r * 128) + (((uint32_t)lane >> 4) << 4);
        amask[mi] = ((uint32_t)(r & 7)) << 4;
    }
    uint32_t bbase[2], bmask[2];
#pragma unroll
    for (int ni = 0; ni < 2; ni++) {
        int r = wn + ni * 16 + (lane & 7) + (((lane >> 4) & 1) << 3);
        bbase[ni] = (uint32_t)(r * 128) + ((((uint32_t)lane >> 3) & 1) << 4);
        bmask[ni] = ((uint32_t)(r & 7)) << 4;
    }

    float acc[4][4][4];
#pragma unroll
    for (int mi = 0; mi < 4; mi++)
#pragma unroll
        for (int nj = 0; nj < 4; nj++)
#pragma unroll
            for (int q = 0; q < 4; q++) acc[mi][nj][q] = 0.f;

    // ------------------------------ pipeline --------------------------------
    load_stage(0, 0);  CP_COMMIT();
    load_stage(1, 64); CP_COMMIT();

#pragma unroll 1
    for (int c = 0; c < NCHUNK; c++) {
        CP_WAIT1();
        __syncthreads();
        if (c + 2 < NCHUNK) load_stage((c + 2) % 3, (c + 2) * 64);
        CP_COMMIT();

        const uint32_t sA = sdyn + (uint32_t)(c % 3) * STAGE;
        const uint32_t sAl = sA + 16384, sBh = sA + 32768, sBl = sA + 49152;
#pragma unroll
        for (int ks = 0; ks < 4; ks++) {
            uint32_t ah[4][4], al[4][4], bh[2][4], bl[2][4];
#pragma unroll
            for (int mi = 0; mi < 4; mi++) {
                uint32_t o = (abase[mi] + ks * 32) ^ amask[mi];
                LDMX4(ah[mi], sA  + o);
                LDMX4(al[mi], sAl + o);
            }
#pragma unroll
            for (int ni = 0; ni < 2; ni++) {
                uint32_t o = (bbase[ni] + ks * 32) ^ bmask[ni];
                LDMX4(bh[ni], sBh + o);
                LDMX4(bl[ni], sBl + o);
            }
#pragma unroll
            for (int mi = 0; mi < 4; mi++)
#pragma unroll
                for (int nj = 0; nj < 4; nj++) {
                    const int g = nj >> 1, h2 = (nj & 1) * 2;
                    MMA16816(acc[mi][nj], ah[mi], bh[g][h2], bh[g][h2 + 1]);
                    MMA16816(acc[mi][nj], ah[mi], bl[g][h2], bl[g][h2 + 1]);
                    MMA16816(acc[mi][nj], al[mi], bh[g][h2], bh[g][h2 + 1]);
                }
        }
    }

    // ------------------------------ epilogue --------------------------------
#pragma unroll
    for (int mi = 0; mi < 4; mi++) {
#pragma unroll
        for (int half = 0; half < 2; half++) {
            const int r = rt * 128 + wm + mi * 16 + (lane >> 2) + half * 8;
            if (r >= cnt) continue;
            const int q0 = half * 2;           // acc regs {0,1} or {2,3}
            if (MODE == 1) {
                size_t rowb = ((size_t)e * N_TOK + r) * (size_t)HID;
#pragma unroll
                for (int nj = 0; nj < 4; nj++) {
                    int col = nt * 128 + wn + nj * 8 + 2 * (lane & 3);
                    float v0 = fmaxf(acc[mi][nj][q0]     + bias[e * HID + col],     0.f);
                    float v1 = fmaxf(acc[mi][nj][q0 + 1] + bias[e * HID + col + 1], 0.f);
                    __nv_bfloat16 h0 = __float2bfloat16(v0);
                    __nv_bfloat16 h1 = __float2bfloat16(v1);
                    __nv_bfloat162 hv; hv.x = h0; hv.y = h1;
                    __nv_bfloat162 lv;
                    lv.x = __float2bfloat16(v0 - __bfloat162float(h0));
                    lv.y = __float2bfloat16(v1 - __bfloat162float(h1));
                    *(__nv_bfloat162*)(g_h_hi + rowb + col) = hv;
                    *(__nv_bfloat162*)(g_h_lo + rowb + col) = lv;
                }
            } else {
                int   tok = g_tok[e * N_TOK + r];
                int   pos = g_pos[e * N_TOK + r];
                float w   = g_wt [e * N_TOK + r];
                float* yrow = g_y + ((size_t)tok * 2 + pos) * (size_t)DIM;
#pragma unroll
                for (int nj = 0; nj < 4; nj++) {
                    int col = nt * 128 + wn + nj * 8 + 2 * (lane & 3);
                    float2 yv;
                    yv.x = w * (acc[mi][nj][q0]     + bias[e * DIM + col]);
                    yv.y = w * (acc[mi][nj][q0 + 1] + bias[e * DIM + col + 1]);
                    *(float2*)(yrow + col) = yv;
                }
            }
        }
    }
}

// ---------------------------------------------------------------------------
// Combine: out[n] = y_part0[n] + y_part1[n]  (fully overwrites d_out)
// ---------------------------------------------------------------------------
__global__ void combine_kernel(float* __restrict__ out) {
    size_t i = (size_t)blockIdx.x * blockDim.x + threadIdx.x;   // float4 units
    size_t n = i / (DIM / 4), d = i % (DIM / 4);
    const float4* a = (const float4*)(g_y + (2 * n) * DIM) + d;
    const float4* b = (const float4*)(g_y + (2 * n + 1) * DIM) + d;
    float4 va = *a, vb = *b, o;
    o.x = va.x + vb.x; o.y = va.y + vb.y; o.z = va.z + vb.z; o.w = va.w + vb.w;
    ((float4*)out)[i] = o;
}

// ---------------------------------------------------------------------------
extern "C" void kernel_launch(void* const* d_in, const int* /*in_sizes*/, int /*n_in*/,
                              void* d_out, int /*out_size*/) {
    const float* x  = (const float*)d_in[0];
    const float* Wg = (const float*)d_in[1];
    const float* bg = (const float*)d_in[2];
    const float* W1 = (const float*)d_in[3];
    const float* b1 = (const float*)d_in[4];
    const float* W2 = (const float*)d_in[5];
    const float* b2 = (const float*)d_in[6];
    float* out = (float*)d_out;

    const int SMEM = 3 * 65536;   // 196608 B
    static bool attr_set = false;
    if (!attr_set) {
        cudaFuncSetAttribute(moe_hmma<1>, cudaFuncAttributeMaxDynamicSharedMemorySize, SMEM);
        cudaFuncSetAttribute(moe_hmma<2>, cudaFuncAttributeMaxDynamicSharedMemorySize, SMEM);
        attr_set = true;
    }

    initcnt_kernel<<<1, 32>>>();
    gate_kernel<<<N_TOK / 8, 256>>>(x, Wg, bg);
    split_x_kernel<<<(N_TOK * DIM) / 256, 256>>>(x);
    wsplit_kernel<<<dim3(HID / 32, DIM / 32, NEXP), dim3(32, 8)>>>(W1, DIM, HID, 1);
    wsplit_kernel<<<dim3(DIM / 32, HID / 32, NEXP), dim3(32, 8)>>>(W2, HID, DIM, 2);

    moe_hmma<1><<<dim3(HID / 128, N_TOK / 128, NEXP), 256, SMEM>>>(b1);
    moe_hmma<2><<<dim3(DIM / 128, N_TOK / 128, NEXP), 256, SMEM>>>(b2);

    combine_kernel<<<(N_TOK * DIM / 4) / 256, 256>>>(out);
}

// round 5
// speedup vs baseline: 3.9088x; 1.4868x over previous
#include <cuda_runtime.h>
#include <cuda_fp16.h>
#include <cstdint>
#include <cstddef>

static constexpr int N_TOK = 4096;
static constexpr int DIM   = 1024;
static constexpr int HID   = 4096;
static constexpr int NEXP  = 8;

// ---------------------------------------------------------------------------
// Static device scratch (allocation-free, graph-safe)
// ---------------------------------------------------------------------------
__device__ int   g_cnt[NEXP];
__device__ int   g_tok[NEXP * N_TOK];
__device__ int   g_pos[NEXP * N_TOK];
__device__ float g_wt [NEXP * N_TOK];

__device__ __align__(16) __half g_x_hi[(size_t)N_TOK * DIM];
__device__ __align__(16) __half g_x_lo[(size_t)N_TOK * DIM];
__device__ __align__(16) __half g_w1  [(size_t)NEXP * HID * DIM];  // [E][H][D] K-major
__device__ __align__(16) __half g_w2  [(size_t)NEXP * DIM * HID];  // [E][D][H] K-major
__device__ __align__(16) __half g_h_hi[(size_t)NEXP * N_TOK * HID];
__device__ __align__(16) __half g_h_lo[(size_t)NEXP * N_TOK * HID];
__device__ __align__(16) float  g_y   [(size_t)2 * N_TOK * DIM];

// ---------------------------------------------------------------------------
// PTX helpers (sm_80-level: compile under target sm_103 without 'a')
// ---------------------------------------------------------------------------
__device__ __forceinline__ uint32_t smem_u32(const void* p) {
    uint32_t a;
    asm("{ .reg .u64 t; cvta.to.shared.u64 t, %1; cvt.u32.u64 %0, t; }" : "=r"(a) : "l"(p));
    return a;
}
#define CP_ASYNC16(dst, src) \
    asm volatile("cp.async.cg.shared.global [%0], [%1], 16;" :: "r"(dst), "l"(src))
#define CP_COMMIT() asm volatile("cp.async.commit_group;" ::: "memory")
#define CP_WAIT1()  asm volatile("cp.async.wait_group 1;" ::: "memory")

#define LDMX4(r, a)                                                              \
    asm volatile("ldmatrix.sync.aligned.m8n8.x4.shared.b16 {%0,%1,%2,%3}, [%4];" \
        : "=r"((r)[0]), "=r"((r)[1]), "=r"((r)[2]), "=r"((r)[3]) : "r"(a))

#define MMA16816(d, a, b0, b1)                                                   \
    asm volatile("mma.sync.aligned.m16n8k16.row.col.f32.f16.f16.f32 "            \
        "{%0,%1,%2,%3},{%4,%5,%6,%7},{%8,%9},{%0,%1,%2,%3};"                     \
        : "+f"((d)[0]), "+f"((d)[1]), "+f"((d)[2]), "+f"((d)[3])                 \
        : "r"((a)[0]), "r"((a)[1]), "r"((a)[2]), "r"((a)[3]), "r"(b0), "r"(b1))

__device__ __forceinline__ uint32_t sw128(uint32_t off) {
    return off ^ ((off >> 3) & 0x70);
}

// ---------------------------------------------------------------------------
__global__ void initcnt_kernel() {
    if (threadIdx.x < NEXP) g_cnt[threadIdx.x] = 0;
}

// ---------------------------------------------------------------------------
// Gating: 1 warp/token, softmax(8), top-2, scatter + position tag
// ---------------------------------------------------------------------------
__global__ void gate_kernel(const float* __restrict__ x,
                            const float* __restrict__ Wg,
                            const float* __restrict__ bg) {
    int warp = (blockIdx.x * blockDim.x + threadIdx.x) >> 5;
    int lane = threadIdx.x & 31;
    if (warp >= N_TOK) return;
    const float* xr = x + (long long)warp * DIM;

    float acc[NEXP];
#pragma unroll
    for (int e = 0; e < NEXP; e++) acc[e] = 0.f;
    for (int d = lane; d < DIM; d += 32) {
        float xv = xr[d];
        const float* wr = Wg + d * NEXP;
#pragma unroll
        for (int e = 0; e < NEXP; e++) acc[e] += xv * wr[e];
    }
#pragma unroll
    for (int off = 16; off > 0; off >>= 1)
#pragma unroll
        for (int e = 0; e < NEXP; e++)
            acc[e] += __shfl_down_sync(0xffffffffu, acc[e], off);

    if (lane == 0) {
        float m = -1e30f;
#pragma unroll
        for (int e = 0; e < NEXP; e++) { acc[e] += bg[e]; m = fmaxf(m, acc[e]); }
        float p[NEXP]; float s = 0.f;
#pragma unroll
        for (int e = 0; e < NEXP; e++) { p[e] = expf(acc[e] - m); s += p[e]; }
        float inv = 1.f / s;
        int e0 = 0; float v0 = p[0];
#pragma unroll
        for (int e = 1; e < NEXP; e++) if (p[e] > v0) { v0 = p[e]; e0 = e; }
        int e1 = -1; float v1 = -1.f;
#pragma unroll
        for (int e = 0; e < NEXP; e++) if (e != e0 && p[e] > v1) { v1 = p[e]; e1 = e; }

        int s0 = atomicAdd(&g_cnt[e0], 1);
        g_tok[e0 * N_TOK + s0] = warp;
        g_wt [e0 * N_TOK + s0] = v0 * inv;
        g_pos[e0 * N_TOK + s0] = 0;
        int s1 = atomicAdd(&g_cnt[e1], 1);
        g_tok[e1 * N_TOK + s1] = warp;
        g_wt [e1 * N_TOK + s1] = v1 * inv;
        g_pos[e1 * N_TOK + s1] = 1;
    }
}

// ---------------------------------------------------------------------------
// fp32 -> fp16 hi/lo split for x
// ---------------------------------------------------------------------------
__global__ void split_x_kernel(const float* __restrict__ x) {
    size_t i = (size_t)blockIdx.x * blockDim.x + threadIdx.x;
    float v = x[i];
    __half h = __float2half_rn(v);
    g_x_hi[i] = h;
    g_x_lo[i] = __float2half_rn(v - __half2float(h));
}

// ---------------------------------------------------------------------------
// Weight transpose + fp16 cast:  in [E][R][C] fp32 -> out [E][C][R] fp16
// block (32,8): 32x32 tile.  Vectorized 8B stores (4 fp16).
// ---------------------------------------------------------------------------
__global__ void wtrans_kernel(const float* __restrict__ in, int R, int C, int which) {
    __shared__ float t[32][33];
    __half* dst = (which == 1) ? g_w1 : g_w2;
    int e  = blockIdx.z;
    int r0 = blockIdx.y * 32, c0 = blockIdx.x * 32;
    const float* src = in + (size_t)e * R * C;
    for (int j = threadIdx.y; j < 32; j += 8)
        t[j][threadIdx.x] = src[(size_t)(r0 + j) * C + c0 + threadIdx.x];
    __syncthreads();
    // 256 threads: row j = tid>>3 (0..31), seg = tid&7 -> 4 fp16 along R
    int tid = threadIdx.y * 32 + threadIdx.x;
    int j   = tid >> 3;
    int seg = (tid & 7) * 4;
    __half2 o0, o1;
    o0.x = __float2half_rn(t[seg + 0][j]);
    o0.y = __float2half_rn(t[seg + 1][j]);
    o1.x = __float2half_rn(t[seg + 2][j]);
    o1.y = __float2half_rn(t[seg + 3][j]);
    size_t ob = (size_t)e * C * R + (size_t)(c0 + j) * R + r0 + seg;
    *(uint2*)(dst + ob) = make_uint2(*(uint32_t*)&o0, *(uint32_t*)&o1);
}

// ---------------------------------------------------------------------------
// Grouped HMMA GEMM.  CTA tile 128(M) x 256(N), K-chunk 64, 3-stage cp.async
// pipeline, 8 warps (2x4), warp tile 64x64, mma.m16n8k16 fp16, fp32 acc.
// 2 products: Ahi*B + Alo*B  (B single fp16).
// MODE 1: h = relu(x@W1t + b1) -> g_h hi/lo        (A = gathered x rows)
// MODE 2: g_y[tok*2+pos] = w*(h@W2t + b2)          (A = g_h slots)
// ---------------------------------------------------------------------------
template <int MODE>
__global__ __launch_bounds__(256, 1)
void moe_hmma(const float* __restrict__ bias) {
    constexpr int K      = (MODE == 1) ? DIM : HID;
    constexpr int NCOL   = (MODE == 1) ? HID : DIM;
    constexpr int NCHUNK = K / 64;
    constexpr uint32_t STAGE = 65536;   // Ahi 16K | Alo 16K | B 32K

    const int e   = blockIdx.z;
    const int cnt = g_cnt[e];
    const int rt  = blockIdx.y;
    if (rt * 128 >= cnt) return;
    const int nt = blockIdx.x;

    extern __shared__ char smem[];
    const uint32_t sdyn = smem_u32(smem);
    const int tid  = threadIdx.x;
    const int lane = tid & 31;
    const int wid  = tid >> 5;
    const int wm = (wid & 1) * 64;
    const int wn = (wid >> 1) * 64;

    const __half* Ahi = (MODE == 1) ? g_x_hi : g_h_hi;
    const __half* Alo = (MODE == 1) ? g_x_lo : g_h_lo;
    const __half* B   = (MODE == 1) ? g_w1   : g_w2;
    const ptrdiff_t dAb = (const char*)Alo - (const char*)Ahi;

    // ------------------- cp.async load plan (per thread) --------------------
    const int u16 = (tid & 7) * 16;           // byte offset within 128B row
    const char* ap[4];
    uint32_t    dstA[4];
#pragma unroll
    for (int i = 0; i < 4; i++) {
        int r    = (tid >> 3) + 32 * i;       // 0..127
        int slot = rt * 128 + r; if (slot >= cnt) slot = cnt - 1;
        size_t arow = (MODE == 1) ? (size_t)g_tok[e * N_TOK + slot]
                                  : ((size_t)e * N_TOK + slot);
        ap[i]   = (const char*)(Ahi + arow * (size_t)K) + u16;
        dstA[i] = sw128((uint32_t)(r * 128) + (uint32_t)u16);
    }
    const char* bp0 = (const char*)(B + ((size_t)e * NCOL + (size_t)nt * 256
                                         + (size_t)(tid >> 3)) * (size_t)K) + u16;
    const uint32_t dstB0 = sw128((uint32_t)((tid >> 3) * 128) + (uint32_t)u16);
    constexpr size_t BROWSTEP = (size_t)32 * K * 2;   // 32 rows

    auto load_stage = [&](int s, int k0) {
        uint32_t st = sdyn + (uint32_t)s * STAGE;
        int kb = k0 * 2;
#pragma unroll
        for (int i = 0; i < 4; i++) {
            CP_ASYNC16(st + dstA[i],         ap[i] + kb);
            CP_ASYNC16(st + 16384 + dstA[i], ap[i] + dAb + kb);
        }
#pragma unroll
        for (int i = 0; i < 8; i++)
            CP_ASYNC16(st + 32768 + dstB0 + (uint32_t)i * 4096, bp0 + i * BROWSTEP + kb);
    };

    // ------------------- ldmatrix address precompute ------------------------
    uint32_t abase[4], amask[4];
#pragma unroll
    for (int mi = 0; mi < 4; mi++) {
        int r = wm + mi * 16 + (lane & 15);
        abase[mi] = (uint32_t)(r * 128) + (((uint32_t)lane >> 4) << 4);
        amask[mi] = ((uint32_t)(r & 7)) << 4;
    }
    uint32_t bbase[4], bmask[4];
#pragma unroll
    for (int g = 0; g < 4; g++) {
        int r = wn + g * 16 + (lane & 7) + (((lane >> 4) & 1) << 3);
        bbase[g] = (uint32_t)(r * 128) + ((((uint32_t)lane >> 3) & 1) << 4);
        bmask[g] = ((uint32_t)(r & 7)) << 4;
    }

    float acc[4][8][4];
#pragma unroll
    for (int mi = 0; mi < 4; mi++)
#pragma unroll
        for (int nj = 0; nj < 8; nj++)
#pragma unroll
            for (int q = 0; q < 4; q++) acc[mi][nj][q] = 0.f;

    // ------------------------------ pipeline --------------------------------
    load_stage(0, 0);  CP_COMMIT();
    load_stage(1, 64); CP_COMMIT();

#pragma unroll 1
    for (int c = 0; c < NCHUNK; c++) {
        CP_WAIT1();
        __syncthreads();
        if (c + 2 < NCHUNK) load_stage((c + 2) % 3, (c + 2) * 64);
        CP_COMMIT();

        const uint32_t sA = sdyn + (uint32_t)(c % 3) * STAGE;
        const uint32_t sAl = sA + 16384, sB = sA + 32768;
#pragma unroll
        for (int ks = 0; ks < 4; ks++) {
            uint32_t ah[4][4], al[4][4], b[4][4];
#pragma unroll
            for (int mi = 0; mi < 4; mi++) {
                uint32_t o = (abase[mi] + ks * 32) ^ amask[mi];
                LDMX4(ah[mi], sA  + o);
                LDMX4(al[mi], sAl + o);
            }
#pragma unroll
            for (int g = 0; g < 4; g++) {
                uint32_t o = (bbase[g] + ks * 32) ^ bmask[g];
                LDMX4(b[g], sB + o);
            }
#pragma unroll
            for (int mi = 0; mi < 4; mi++)
#pragma unroll
                for (int nj = 0; nj < 8; nj++) {
                    const int g = nj >> 1, h2 = (nj & 1) * 2;
                    MMA16816(acc[mi][nj], ah[mi], b[g][h2], b[g][h2 + 1]);
                    MMA16816(acc[mi][nj], al[mi], b[g][h2], b[g][h2 + 1]);
                }
        }
    }

    // ------------------------------ epilogue --------------------------------
#pragma unroll
    for (int mi = 0; mi < 4; mi++) {
#pragma unroll
        for (int half = 0; half < 2; half++) {
            const int r = rt * 128 + wm + mi * 16 + (lane >> 2) + half * 8;
            if (r >= cnt) continue;
            const int q0 = half * 2;
            if (MODE == 1) {
                size_t rowb = ((size_t)e * N_TOK + r) * (size_t)HID;
#pragma unroll
                for (int nj = 0; nj < 8; nj++) {
                    int col = nt * 256 + wn + nj * 8 + 2 * (lane & 3);
                    float v0 = fmaxf(acc[mi][nj][q0]     + bias[e * HID + col],     0.f);
                    float v1 = fmaxf(acc[mi][nj][q0 + 1] + bias[e * HID + col + 1], 0.f);
                    __half h0 = __float2half_rn(v0);
                    __half h1 = __float2half_rn(v1);
                    __half2 hv; hv.x = h0; hv.y = h1;
                    __half2 lv;
                    lv.x = __float2half_rn(v0 - __half2float(h0));
                    lv.y = __float2half_rn(v1 - __half2float(h1));
                    *(__half2*)(g_h_hi + rowb + col) = hv;
                    *(__half2*)(g_h_lo + rowb + col) = lv;
                }
            } else {
                int   tok = g_tok[e * N_TOK + r];
                int   pos = g_pos[e * N_TOK + r];
                float w   = g_wt [e * N_TOK + r];
                float* yrow = g_y + ((size_t)tok * 2 + pos) * (size_t)DIM;
#pragma unroll
                for (int nj = 0; nj < 8; nj++) {
                    int col = nt * 256 + wn + nj * 8 + 2 * (lane & 3);
                    float2 yv;
                    yv.x = w * (acc[mi][nj][q0]     + bias[e * DIM + col]);
                    yv.y = w * (acc[mi][nj][q0 + 1] + bias[e * DIM + col + 1]);
                    *(float2*)(yrow + col) = yv;
                }
            }
        }
    }
}

// ---------------------------------------------------------------------------
// Combine: out[n] = y_part0[n] + y_part1[n]  (fully overwrites d_out)
// ---------------------------------------------------------------------------
__global__ void combine_kernel(float* __restrict__ out) {
    size_t i = (size_t)blockIdx.x * blockDim.x + threadIdx.x;   // float4 units
    size_t n = i / (DIM / 4), d = i % (DIM / 4);
    const float4* a = (const float4*)(g_y + (2 * n) * DIM) + d;
    const float4* b = (const float4*)(g_y + (2 * n + 1) * DIM) + d;
    float4 va = *a, vb = *b, o;
    o.x = va.x + vb.x; o.y = va.y + vb.y; o.z = va.z + vb.z; o.w = va.w + vb.w;
    ((float4*)out)[i] = o;
}

// ---------------------------------------------------------------------------
extern "C" void kernel_launch(void* const* d_in, const int* /*in_sizes*/, int /*n_in*/,
                              void* d_out, int /*out_size*/) {
    const float* x  = (const float*)d_in[0];
    const float* Wg = (const float*)d_in[1];
    const float* bg = (const float*)d_in[2];
    const float* W1 = (const float*)d_in[3];
    const float* b1 = (const float*)d_in[4];
    const float* W2 = (const float*)d_in[5];
    const float* b2 = (const float*)d_in[6];
    float* out = (float*)d_out;

    const int SMEM = 3 * 65536;   // 196608 B
    static bool attr_set = false;
    if (!attr_set) {
        cudaFuncSetAttribute(moe_hmma<1>, cudaFuncAttributeMaxDynamicSharedMemorySize, SMEM);
        cudaFuncSetAttribute(moe_hmma<2>, cudaFuncAttributeMaxDynamicSharedMemorySize, SMEM);
        attr_set = true;
    }

    initcnt_kernel<<<1, 32>>>();
    gate_kernel<<<N_TOK / 8, 256>>>(x, Wg, bg);
    split_x_kernel<<<(N_TOK * DIM) / 256, 256>>>(x);
    wtrans_kernel<<<dim3(HID / 32, DIM / 32, NEXP), dim3(32, 8)>>>(W1, DIM, HID, 1);
    wtrans_kernel<<<dim3(DIM / 32, HID / 32, NEXP), dim3(32, 8)>>>(W2, HID, DIM, 2);

    moe_hmma<1><<<dim3(HID / 256, N_TOK / 128, NEXP), 256, SMEM>>>(b1);
    moe_hmma<2><<<dim3(DIM / 256, N_TOK / 128, NEXP), 256, SMEM>>>(b2);

    combine_kernel<<<(N_TOK * DIM / 4) / 256, 256>>>(out);
}